// round 1
// baseline (speedup 1.0000x reference)
#include <cuda_runtime.h>
#include <cfloat>

#define Bn 16
#define Cn 64
#define Nn 2048
#define On 64
#define Kn 20
#define CNT_TOT (16*2048*20)

// ---------------- scratch (static device globals; no runtime allocation) ----------------
__device__ float  g_D[(size_t)Bn*Nn*Nn];     // 256 MB neg_dist scratch
__device__ float  g_xx[Bn*Nn];               // squared norms
__device__ int    g_idx[Bn*Nn*Kn];           // top-K indices
__device__ float  g_U[(size_t)Bn*Nn*On];     // U[b][m][o] = Wd . x  (o contiguous)
__device__ float  g_Bse[(size_t)Bn*Nn*On];   // (V-U)[b][n][o]
__device__ double g_sum[On], g_sumsq[On];
__device__ float  g_scale[On], g_shift[On];

// ---------------- kernel 0: zero the stats accumulators (graph replays!) ----------------
__global__ void k_zero() {
    int o = threadIdx.x;
    g_sum[o] = 0.0; g_sumsq[o] = 0.0;
}

// ---------------- kernel 1: xx[b,n] = sum_c x^2 ----------------
__global__ void k_xx(const float* __restrict__ x) {
    int id = blockIdx.x * blockDim.x + threadIdx.x;   // 0 .. B*N-1
    if (id >= Bn * Nn) return;
    int b = id / Nn, n = id % Nn;
    const float* xp = x + (size_t)b * Cn * Nn + n;
    float s = 0.f;
#pragma unroll
    for (int c = 0; c < Cn; c++) {
        float v = xp[(size_t)c * Nn];
        s = fmaf(v, v, s);
    }
    g_xx[id] = s;
}

// ---------------- kernel 2: neg_dist tiles (symmetric: compute tm>=tn, write both) ------
__global__ void k_gram(const float* __restrict__ x) {
    int tm = blockIdx.x, tn = blockIdx.y, b = blockIdx.z;
    if (tm < tn) return;
    __shared__ float sh[8192];                 // As[4096] | Bs[4096]; reused as Ts[64*65]
    float* As = sh;
    float* Bs = sh + 4096;
    int n0 = tn * 64, m0 = tm * 64;
    const float* xb = x + (size_t)b * Cn * Nn;
    int tid = threadIdx.x;
#pragma unroll
    for (int i = 0; i < 16; i++) {
        int id = tid + 256 * i;
        int c = id >> 6, col = id & 63;
        As[id] = xb[(size_t)c * Nn + n0 + col];
        Bs[id] = xb[(size_t)c * Nn + m0 + col];
    }
    __syncthreads();

    int tx = tid & 15, ty = tid >> 4;
    float acc[4][4] = {};
#pragma unroll 8
    for (int c = 0; c < 64; c++) {
        float4 a  = *(const float4*)(As + c * 64 + ty * 4);
        float4 bb = *(const float4*)(Bs + c * 64 + tx * 4);
        float av[4] = {a.x, a.y, a.z, a.w};
        float bv[4] = {bb.x, bb.y, bb.z, bb.w};
#pragma unroll
        for (int i = 0; i < 4; i++)
#pragma unroll
            for (int j = 0; j < 4; j++)
                acc[i][j] = fmaf(av[i], bv[j], acc[i][j]);
    }

    float xn[4], xm[4];
#pragma unroll
    for (int i = 0; i < 4; i++) {
        xn[i] = g_xx[b * Nn + n0 + ty * 4 + i];
        xm[i] = g_xx[b * Nn + m0 + tx * 4 + i];
    }

    float* Db = g_D + (size_t)b * Nn * Nn;
    __syncthreads();                           // done reading As/Bs; sh becomes Ts
    float* Ts = sh;                            // 64 x 65

#pragma unroll
    for (int i = 0; i < 4; i++) {
        float vv[4];
#pragma unroll
        for (int j = 0; j < 4; j++)
            vv[j] = 2.f * acc[i][j] - xn[i] - xm[j];
        *(float4*)&Db[(size_t)(n0 + ty * 4 + i) * Nn + m0 + tx * 4] =
            make_float4(vv[0], vv[1], vv[2], vv[3]);
        if (tm != tn) {
#pragma unroll
            for (int j = 0; j < 4; j++)
                Ts[(ty * 4 + i) * 65 + tx * 4 + j] = vv[j];
        }
    }

    if (tm != tn) {                            // uniform branch; coalesced transposed write
        __syncthreads();
#pragma unroll
        for (int i = 0; i < 4; i++) {
            int r = ty * 4 + i;                // m-local row
            float4 w = make_float4(Ts[(tx * 4 + 0) * 65 + r],
                                   Ts[(tx * 4 + 1) * 65 + r],
                                   Ts[(tx * 4 + 2) * 65 + r],
                                   Ts[(tx * 4 + 3) * 65 + r]);
            *(float4*)&Db[(size_t)(m0 + r) * Nn + n0 + tx * 4] = w;
        }
    }
}

// ---------------- kernel 3: top-K=20 per row (iterative block argmax) ----------------
__global__ void k_topk() {
    int row = blockIdx.x;                       // b*N + n
    const float* d = g_D + (size_t)row * Nn;
    int tid = threadIdx.x;                      // 256
    float v[8];
#pragma unroll
    for (int i = 0; i < 8; i++) v[i] = d[tid + 256 * i];

    __shared__ float sv[8];
    __shared__ int   si[8];
    __shared__ int   swin;
    int* op = g_idx + row * Kn;

    for (int k = 0; k < Kn; k++) {
        float bv = -FLT_MAX;
        int   bi = 0x7fffffff;
#pragma unroll
        for (int i = 0; i < 8; i++) {
            int e = tid + (i << 8);
            if (v[i] > bv) { bv = v[i]; bi = e; }   // i ascending -> keeps smallest e on tie
        }
#pragma unroll
        for (int off = 16; off; off >>= 1) {
            float ov = __shfl_down_sync(0xffffffffu, bv, off);
            int   oi = __shfl_down_sync(0xffffffffu, bi, off);
            if (ov > bv || (ov == bv && oi < bi)) { bv = ov; bi = oi; }
        }
        if ((tid & 31) == 0) { sv[tid >> 5] = bv; si[tid >> 5] = bi; }
        __syncthreads();
        if (tid == 0) {
            float fv = sv[0]; int fi = si[0];
#pragma unroll
            for (int w = 1; w < 8; w++)
                if (sv[w] > fv || (sv[w] == fv && si[w] < fi)) { fv = sv[w]; fi = si[w]; }
            swin = fi;
            op[k] = fi;
        }
        __syncthreads();
        int w = swin;
        if ((w & 255) == tid) v[w >> 8] = -FLT_MAX;
    }
}

// ---------------- kernel 4: U = Wd.x , Bse = (Wc-Wd).x  (o-contiguous layout) -----------
__global__ void k_uv(const float* __restrict__ x, const float* __restrict__ W) {
    int b = blockIdx.y;
    int m0 = blockIdx.x * 64;
    __shared__ float Wd[64 * 64];   // [c][o]
    __shared__ float Wf[64 * 64];   // [c][o]  (Wc - Wd)
    __shared__ float xs[64 * 64];   // [c][m]
    int tid = threadIdx.x;
#pragma unroll
    for (int i = 0; i < 16; i++) {
        int id = tid + 256 * i;
        int o = id >> 6, c = id & 63;
        float wd = W[o * 128 + c];
        float wc = W[o * 128 + 64 + c];
        Wd[c * 64 + o] = wd;
        Wf[c * 64 + o] = wc - wd;
        // xs: id -> (c2 = id>>6, m = id&63)
        xs[id] = x[(size_t)b * Cn * Nn + (size_t)(id >> 6) * Nn + m0 + (id & 63)];
    }
    __syncthreads();

    int o = tid & 63, mq = tid >> 6;
    float aU[16], aD[16];
#pragma unroll
    for (int t = 0; t < 16; t++) { aU[t] = 0.f; aD[t] = 0.f; }

    for (int c = 0; c < 64; c++) {
        float wu = Wd[c * 64 + o];
        float wf = Wf[c * 64 + o];
#pragma unroll
        for (int t = 0; t < 16; t++) {
            float xv = xs[c * 64 + mq + t * 4];   // broadcast within warp
            aU[t] = fmaf(wu, xv, aU[t]);
            aD[t] = fmaf(wf, xv, aD[t]);
        }
    }
#pragma unroll
    for (int t = 0; t < 16; t++) {
        int m = m0 + mq + t * 4;
        g_U  [((size_t)b * Nn + m) * On + o] = aU[t];
        g_Bse[((size_t)b * Nn + m) * On + o] = aD[t];
    }
}

// ---------------- kernel 5: per-channel sum / sumsq of y over (b,n,k) ----------------
__global__ void k_stats() {
    int b = blockIdx.y;
    int n0 = blockIdx.x * 128;
    int tid = threadIdx.x;
    int o = tid & 63, g = tid >> 6;
    float s = 0.f, s2 = 0.f;
    for (int j = 0; j < 32; j++) {
        int n = n0 + g * 32 + j;
        float bse = g_Bse[((size_t)b * Nn + n) * On + o];
        const int* ip = g_idx + (b * Nn + n) * Kn;
#pragma unroll
        for (int k = 0; k < Kn; k++) {
            int m = ip[k];
            float y = g_U[((size_t)b * Nn + m) * On + o] + bse;
            s += y;
            s2 = fmaf(y, y, s2);
        }
    }
    __shared__ float ss[4][64], ss2[4][64];
    ss[g][o] = s; ss2[g][o] = s2;
    __syncthreads();
    if (g == 0) {
        double ts = (double)ss[0][o] + (double)ss[1][o] + (double)ss[2][o] + (double)ss[3][o];
        double t2 = (double)ss2[0][o] + (double)ss2[1][o] + (double)ss2[2][o] + (double)ss2[3][o];
        atomicAdd(&g_sum[o], ts);
        atomicAdd(&g_sumsq[o], t2);
    }
}

// ---------------- kernel 6: finalize BN affine ----------------
__global__ void k_fin(const float* __restrict__ gamma, const float* __restrict__ beta) {
    int o = threadIdx.x;
    double mean = g_sum[o] / (double)CNT_TOT;
    double var  = g_sumsq[o] / (double)CNT_TOT - mean * mean;
    float sc = gamma[o] * rsqrtf((float)var + 1e-5f);
    g_scale[o] = sc;
    g_shift[o] = beta[o] - (float)mean * sc;
}

// ---------------- kernel 7: normalize + leaky relu + max over k -> out[b][o][n] --------
__global__ void k_out(float* __restrict__ out) {
    int b = blockIdx.y;
    int n0 = blockIdx.x * 32;
    int tid = threadIdx.x;
    int o = tid & 63, nq = tid >> 6;
    __shared__ float sm[64 * 33];
    float sc = g_scale[o], sh = g_shift[o];
    for (int j = 0; j < 8; j++) {
        int nl = nq * 8 + j;
        int n = n0 + nl;
        float bse = g_Bse[((size_t)b * Nn + n) * On + o];
        const int* ip = g_idx + (b * Nn + n) * Kn;
        float mx = -FLT_MAX;
#pragma unroll
        for (int k = 0; k < Kn; k++) {
            int m = ip[k];
            float y  = g_U[((size_t)b * Nn + m) * On + o] + bse;
            float yn = fmaf(y, sc, sh);
            float a  = (yn >= 0.f) ? yn : 0.2f * yn;
            mx = fmaxf(mx, a);
        }
        sm[o * 33 + nl] = mx;
    }
    __syncthreads();
    int nl2 = tid & 31, og = tid >> 5;
#pragma unroll
    for (int j = 0; j < 8; j++) {
        int o2 = og * 8 + j;
        out[((size_t)b * On + o2) * Nn + n0 + nl2] = sm[o2 * 33 + nl2];
    }
}

// ---------------- launch ----------------
extern "C" void kernel_launch(void* const* d_in, const int* in_sizes, int n_in,
                              void* d_out, int out_size) {
    const float* x     = (const float*)d_in[0];
    const float* W     = (const float*)d_in[1];
    const float* gamma = (const float*)d_in[2];
    const float* beta  = (const float*)d_in[3];
    float* out = (float*)d_out;

    k_zero<<<1, 64>>>();
    k_xx<<<(Bn * Nn) / 256, 256>>>(x);

    dim3 gg(32, 32, 16);
    k_gram<<<gg, 256>>>(x);

    k_topk<<<Bn * Nn, 256>>>();

    dim3 guv(Nn / 64, Bn);
    k_uv<<<guv, 256>>>(x, W);

    dim3 gst(16, Bn);
    k_stats<<<gst, 256>>>();

    k_fin<<<1, 64>>>(gamma, beta);

    dim3 go(Nn / 32, Bn);
    k_out<<<go, 256>>>(out);
}

// round 2
// speedup vs baseline: 1.9119x; 1.9119x over previous
#include <cuda_runtime.h>
#include <cfloat>

#define Bn 16
#define Cn 64
#define Nn 2048
#define On 64
#define Kn 20
#define CNT_TOT (16*2048*20)

// ---------------- scratch (static device globals; no runtime allocation) ----------------
__device__ float  g_D[(size_t)Bn*Nn*Nn];     // 256 MB neg_dist scratch
__device__ float  g_xx[Bn*Nn];               // squared norms
__device__ int    g_idx[Bn*Nn*Kn];           // top-K index sets (order arbitrary)
__device__ float  g_U[(size_t)Bn*Nn*On];     // U[b][m][o] = Wd . x  (o contiguous)
__device__ float  g_Bse[(size_t)Bn*Nn*On];   // (V-U)[b][n][o]
__device__ double g_sum[On], g_sumsq[On];
__device__ float  g_scale[On], g_shift[On];

// ---------------- kernel 0: zero the stats accumulators (graph replays!) ----------------
__global__ void k_zero() {
    int o = threadIdx.x;
    g_sum[o] = 0.0; g_sumsq[o] = 0.0;
}

// ---------------- kernel 1: xx[b,n] = sum_c x^2 ----------------
__global__ void k_xx(const float* __restrict__ x) {
    int id = blockIdx.x * blockDim.x + threadIdx.x;   // 0 .. B*N-1
    if (id >= Bn * Nn) return;
    int b = id / Nn, n = id % Nn;
    const float* xp = x + (size_t)b * Cn * Nn + n;
    float s = 0.f;
#pragma unroll
    for (int c = 0; c < Cn; c++) {
        float v = xp[(size_t)c * Nn];
        s = fmaf(v, v, s);
    }
    g_xx[id] = s;
}

// ---------------- kernel 2: neg_dist tiles (symmetric: compute tm>=tn, write both) ------
__global__ void k_gram(const float* __restrict__ x) {
    int tm = blockIdx.x, tn = blockIdx.y, b = blockIdx.z;
    if (tm < tn) return;
    __shared__ float sh[8192];                 // As[4096] | Bs[4096]; reused as Ts[64*65]
    float* As = sh;
    float* Bs = sh + 4096;
    int n0 = tn * 64, m0 = tm * 64;
    const float* xb = x + (size_t)b * Cn * Nn;
    int tid = threadIdx.x;
#pragma unroll
    for (int i = 0; i < 16; i++) {
        int id = tid + 256 * i;
        int c = id >> 6, col = id & 63;
        As[id] = xb[(size_t)c * Nn + n0 + col];
        Bs[id] = xb[(size_t)c * Nn + m0 + col];
    }
    __syncthreads();

    int tx = tid & 15, ty = tid >> 4;
    float acc[4][4] = {};
#pragma unroll 8
    for (int c = 0; c < 64; c++) {
        float4 a  = *(const float4*)(As + c * 64 + ty * 4);
        float4 bb = *(const float4*)(Bs + c * 64 + tx * 4);
        float av[4] = {a.x, a.y, a.z, a.w};
        float bv[4] = {bb.x, bb.y, bb.z, bb.w};
#pragma unroll
        for (int i = 0; i < 4; i++)
#pragma unroll
            for (int j = 0; j < 4; j++)
                acc[i][j] = fmaf(av[i], bv[j], acc[i][j]);
    }

    float xn[4], xm[4];
#pragma unroll
    for (int i = 0; i < 4; i++) {
        xn[i] = g_xx[b * Nn + n0 + ty * 4 + i];
        xm[i] = g_xx[b * Nn + m0 + tx * 4 + i];
    }

    float* Db = g_D + (size_t)b * Nn * Nn;
    __syncthreads();                           // done reading As/Bs; sh becomes Ts
    float* Ts = sh;                            // 64 x 65

#pragma unroll
    for (int i = 0; i < 4; i++) {
        float vv[4];
#pragma unroll
        for (int j = 0; j < 4; j++)
            vv[j] = 2.f * acc[i][j] - xn[i] - xm[j];
        *(float4*)&Db[(size_t)(n0 + ty * 4 + i) * Nn + m0 + tx * 4] =
            make_float4(vv[0], vv[1], vv[2], vv[3]);
        if (tm != tn) {
#pragma unroll
            for (int j = 0; j < 4; j++)
                Ts[(ty * 4 + i) * 65 + tx * 4 + j] = vv[j];
        }
    }

    if (tm != tn) {                            // uniform branch; coalesced transposed write
        __syncthreads();
#pragma unroll
        for (int i = 0; i < 4; i++) {
            int r = ty * 4 + i;                // m-local row
            float4 w = make_float4(Ts[(tx * 4 + 0) * 65 + r],
                                   Ts[(tx * 4 + 1) * 65 + r],
                                   Ts[(tx * 4 + 2) * 65 + r],
                                   Ts[(tx * 4 + 3) * 65 + r]);
            *(float4*)&Db[(size_t)(m0 + r) * Nn + n0 + tx * 4] = w;
        }
    }
}

// ---------------- kernel 3: top-K=20 per row via 4-pass radix select ----------------
// Downstream only sums/maxes over k, so only the SET of top-K indices matters.
// Ties at the threshold are broken by smallest index (matches stable top_k).
__global__ void k_topk() {
    int row = blockIdx.x;                       // b*N + n
    const float4* d4 = (const float4*)(g_D + (size_t)row * Nn);
    int tid = threadIdx.x;                      // 256 threads, 8 elems each

    // load + convert to order-preserving uint keys (bigger key = bigger float)
    unsigned key[8];
    {
        float4 a = d4[tid * 2], b = d4[tid * 2 + 1];
        float f[8] = {a.x, a.y, a.z, a.w, b.x, b.y, b.z, b.w};
#pragma unroll
        for (int i = 0; i < 8; i++) {
            unsigned u = __float_as_uint(f[i]);
            key[i] = (u & 0x80000000u) ? ~u : (u | 0x80000000u);
        }
    }

    __shared__ int      hist[256];
    __shared__ int      sgt[257];               // suffix counts; sgt[256] = 0
    __shared__ unsigned s_pfx;
    __shared__ int      s_kp;
    __shared__ int      s_cnt, s_tiecnt;
    __shared__ int      s_tiebuf[2048];

    unsigned pfx = 0;
    int kp = Kn;                                // slots still to resolve

#pragma unroll
    for (int p = 3; p >= 0; p--) {
        const int sh = p * 8;
        hist[tid] = 0;
        if (tid == 0) sgt[256] = 0;
        __syncthreads();
#pragma unroll
        for (int i = 0; i < 8; i++) {
            unsigned u = key[i];
            bool match = (p == 3) || ((u >> (sh + 8)) == (pfx >> (sh + 8)));
            if (match) atomicAdd(&hist[(u >> sh) & 255], 1);
        }
        __syncthreads();
        if (tid < 32) {                          // one warp: suffix sums of 256 bins
            int base = tid * 8;
            int loc[8];
            int run = 0;
#pragma unroll
            for (int j = 7; j >= 0; j--) { run += hist[base + j]; loc[j] = run; }
            int tot = run, inc = tot;
#pragma unroll
            for (int off = 1; off < 32; off <<= 1) {
                int v = __shfl_down_sync(0xffffffffu, inc, off);
                if (tid + off < 32) inc += v;
            }
            int above = inc - tot;               // sum over lanes with higher id
#pragma unroll
            for (int j = 0; j < 8; j++) sgt[base + j] = loc[j] + above;
        }
        __syncthreads();
        int cg = sgt[tid], cgn = sgt[tid + 1];   // count >= bucket tid / > bucket tid
        if (cg >= kp && cgn < kp) {              // exactly one thread hits this
            s_pfx = pfx | ((unsigned)tid << sh);
            s_kp  = kp - cgn;
        }
        __syncthreads();
        pfx = s_pfx; kp = s_kp;
        __syncthreads();
    }

    unsigned T = pfx;                            // exact key of the K-th largest
    int tneed = kp;                              // how many ==T to include

    if (tid == 0) { s_cnt = 0; s_tiecnt = 0; }
    __syncthreads();

    int* op = g_idx + row * Kn;
#pragma unroll
    for (int i = 0; i < 8; i++) {
        unsigned u = key[i];
        int e = tid * 8 + i;
        if (u > T) {
            int pos = atomicAdd(&s_cnt, 1);
            op[pos] = e;
        } else if (u == T) {
            int pos = atomicAdd(&s_tiecnt, 1);
            s_tiebuf[pos] = e;
        }
    }
    __syncthreads();
    int base = s_cnt, tc = s_tiecnt;             // base == Kn - tneed
    if (tc == tneed) {                           // common case: exact fit
        for (int j = tid; j < tc; j += 256) op[base + j] = s_tiebuf[j];
    } else if (tid == 0) {                       // rare: pick smallest-index ties
        for (int s = 0; s < tneed; s++) {
            int bm = 0x7fffffff, bj = -1;
            for (int j = 0; j < tc; j++) {
                int v = s_tiebuf[j];
                if (v < bm) { bm = v; bj = j; }
            }
            op[base + s] = bm;
            s_tiebuf[bj] = 0x7fffffff;
        }
    }
}

// ---------------- kernel 4: U = Wd.x , Bse = (Wc-Wd).x  (o-contiguous layout) -----------
__global__ void k_uv(const float* __restrict__ x, const float* __restrict__ W) {
    int b = blockIdx.y;
    int m0 = blockIdx.x * 64;
    __shared__ float Wd[64 * 64];   // [c][o]
    __shared__ float Wf[64 * 64];   // [c][o]  (Wc - Wd)
    __shared__ float xs[64 * 64];   // [c][m]
    int tid = threadIdx.x;
#pragma unroll
    for (int i = 0; i < 16; i++) {
        int id = tid + 256 * i;
        int o = id >> 6, c = id & 63;
        float wd = W[o * 128 + c];
        float wc = W[o * 128 + 64 + c];
        Wd[c * 64 + o] = wd;
        Wf[c * 64 + o] = wc - wd;
        xs[id] = x[(size_t)b * Cn * Nn + (size_t)(id >> 6) * Nn + m0 + (id & 63)];
    }
    __syncthreads();

    int o = tid & 63, mq = tid >> 6;
    float aU[16], aD[16];
#pragma unroll
    for (int t = 0; t < 16; t++) { aU[t] = 0.f; aD[t] = 0.f; }

    for (int c = 0; c < 64; c++) {
        float wu = Wd[c * 64 + o];
        float wf = Wf[c * 64 + o];
#pragma unroll
        for (int t = 0; t < 16; t++) {
            float xv = xs[c * 64 + mq + t * 4];   // broadcast within warp
            aU[t] = fmaf(wu, xv, aU[t]);
            aD[t] = fmaf(wf, xv, aD[t]);
        }
    }
#pragma unroll
    for (int t = 0; t < 16; t++) {
        int m = m0 + mq + t * 4;
        g_U  [((size_t)b * Nn + m) * On + o] = aU[t];
        g_Bse[((size_t)b * Nn + m) * On + o] = aD[t];
    }
}

// ---------------- kernel 5: per-channel sum / sumsq of y over (b,n,k) ----------------
__global__ void k_stats() {
    int b = blockIdx.y;
    int n0 = blockIdx.x * 128;
    int tid = threadIdx.x;
    int o = tid & 63, g = tid >> 6;
    float s = 0.f, s2 = 0.f;
    for (int j = 0; j < 32; j++) {
        int n = n0 + g * 32 + j;
        float bse = g_Bse[((size_t)b * Nn + n) * On + o];
        const int* ip = g_idx + (b * Nn + n) * Kn;
#pragma unroll
        for (int k = 0; k < Kn; k++) {
            int m = ip[k];
            float y = g_U[((size_t)b * Nn + m) * On + o] + bse;
            s += y;
            s2 = fmaf(y, y, s2);
        }
    }
    __shared__ float ss[4][64], ss2[4][64];
    ss[g][o] = s; ss2[g][o] = s2;
    __syncthreads();
    if (g == 0) {
        double ts = (double)ss[0][o] + (double)ss[1][o] + (double)ss[2][o] + (double)ss[3][o];
        double t2 = (double)ss2[0][o] + (double)ss2[1][o] + (double)ss2[2][o] + (double)ss2[3][o];
        atomicAdd(&g_sum[o], ts);
        atomicAdd(&g_sumsq[o], t2);
    }
}

// ---------------- kernel 6: finalize BN affine ----------------
__global__ void k_fin(const float* __restrict__ gamma, const float* __restrict__ beta) {
    int o = threadIdx.x;
    double mean = g_sum[o] / (double)CNT_TOT;
    double var  = g_sumsq[o] / (double)CNT_TOT - mean * mean;
    float sc = gamma[o] * rsqrtf((float)var + 1e-5f);
    g_scale[o] = sc;
    g_shift[o] = beta[o] - (float)mean * sc;
}

// ---------------- kernel 7: normalize + leaky relu + max over k -> out[b][o][n] --------
__global__ void k_out(float* __restrict__ out) {
    int b = blockIdx.y;
    int n0 = blockIdx.x * 32;
    int tid = threadIdx.x;
    int o = tid & 63, nq = tid >> 6;
    __shared__ float sm[64 * 33];
    float sc = g_scale[o], sh = g_shift[o];
    for (int j = 0; j < 8; j++) {
        int nl = nq * 8 + j;
        int n = n0 + nl;
        float bse = g_Bse[((size_t)b * Nn + n) * On + o];
        const int* ip = g_idx + (b * Nn + n) * Kn;
        float mx = -FLT_MAX;
#pragma unroll
        for (int k = 0; k < Kn; k++) {
            int m = ip[k];
            float y  = g_U[((size_t)b * Nn + m) * On + o] + bse;
            float yn = fmaf(y, sc, sh);
            float a  = (yn >= 0.f) ? yn : 0.2f * yn;
            mx = fmaxf(mx, a);
        }
        sm[o * 33 + nl] = mx;
    }
    __syncthreads();
    int nl2 = tid & 31, og = tid >> 5;
#pragma unroll
    for (int j = 0; j < 8; j++) {
        int o2 = og * 8 + j;
        out[((size_t)b * On + o2) * Nn + n0 + nl2] = sm[o2 * 33 + nl2];
    }
}

// ---------------- launch ----------------
extern "C" void kernel_launch(void* const* d_in, const int* in_sizes, int n_in,
                              void* d_out, int out_size) {
    const float* x     = (const float*)d_in[0];
    const float* W     = (const float*)d_in[1];
    const float* gamma = (const float*)d_in[2];
    const float* beta  = (const float*)d_in[3];
    float* out = (float*)d_out;

    k_zero<<<1, 64>>>();
    k_xx<<<(Bn * Nn) / 256, 256>>>(x);

    dim3 gg(32, 32, 16);
    k_gram<<<gg, 256>>>(x);

    k_topk<<<Bn * Nn, 256>>>();

    dim3 guv(Nn / 64, Bn);
    k_uv<<<guv, 256>>>(x, W);

    dim3 gst(16, Bn);
    k_stats<<<gst, 256>>>();

    k_fin<<<1, 64>>>(gamma, beta);

    dim3 go(Nn / 32, Bn);
    k_out<<<go, 256>>>(out);
}